// round 6
// baseline (speedup 1.0000x reference)
#include <cuda_runtime.h>
#include <cstdint>
#include <math.h>

#define N_NODES   100000
#define N_EDGES   200000
#define NNZ       2000000
#define DIM       64
#define HID       32
#define K_KEEP    1000000

// ---------------- device scratch (no allocations allowed) ----------------
struct Ctrl {
    unsigned Tbits;
    int cutoff;
};

__device__ __align__(16) float g_xa[N_NODES * HID];   // x @ W1[:64] + b1
__device__ __align__(16) float g_xb[N_NODES * HID];   // x @ W1[64:]
__device__ __align__(16) float g_eb[N_EDGES * HID];   // segment sums of xb
__device__ int      g_cnt[N_EDGES];
__device__ float    g_sum_p[N_EDGES];
__device__ float    g_sum_s[N_EDGES];
__device__ int      g_cand[NNZ];
__device__ unsigned g_cbits[NNZ];
__device__ int      g_ncand;
__device__ unsigned g_hist0[2048];
__device__ unsigned g_hist1[2048];
__device__ Ctrl     g_ctrl;

// ---------------- shared-mem scan + threshold-bucket pick ----------------
// sA holds the histogram on entry (n elements). Finds bucket where the
// (desc ? suffix : prefix) cumulative first crosses `rank`.
__device__ void pick_bucket(unsigned* sA, unsigned* sB, int n, int rank, bool desc,
                            int* res_i, int* res_rank, int* res_neq) {
    int nt = blockDim.x;
    int tid = threadIdx.x;
    unsigned *in = sA, *out = sB;
    for (int off = 1; off < n; off <<= 1) {
        for (int i = tid; i < n; i += nt) {
            unsigned add = desc ? ((i + off < n) ? in[i + off] : 0u)
                                : ((i >= off) ? in[i - off] : 0u);
            out[i] = in[i] + add;
        }
        __syncthreads();
        unsigned* t = in; in = out; out = t;
    }
    for (int i = tid; i < n; i += nt) {
        unsigned adj = desc ? ((i + 1 < n) ? in[i + 1] : 0u)
                            : ((i > 0) ? in[i - 1] : 0u);
        if ((int)in[i] >= rank && (int)adj < rank) {
            *res_i = i;
            *res_rank = rank - (int)adj;
            *res_neq = (int)(in[i] - adj);
        }
    }
    __syncthreads();
}

// ---------------- pre_a: zero cnt + hists + ctrl (before init's counting) ----------------
__global__ void k_pre_a() {
    int tid = blockIdx.x * blockDim.x + threadIdx.x;
    int nt  = gridDim.x * blockDim.x;
    for (int i = tid; i < N_EDGES; i += nt) g_cnt[i] = 0;
    for (int i = tid; i < 2048; i += nt) { g_hist0[i] = 0u; g_hist1[i] = 0u; }
    if (tid == 0) { g_ctrl.Tbits = 0; g_ctrl.cutoff = 0; g_ncand = 0; }
}

// ---------------- pre_b: zero float sums (before logits / mask) ----------------
__global__ void k_pre_b() {
    int tid = blockIdx.x * blockDim.x + threadIdx.x;
    int nt  = gridDim.x * blockDim.x;
    for (int i = tid; i < N_EDGES; i += nt) { g_sum_p[i] = 0.0f; g_sum_s[i] = 0.0f; }
}

// ---------------- fused: proj | zero eb | count E ----------------
#define PROJ_BLKS 512
#define ZERO_BLKS 128
#define CNT_BLKS  128
__global__ void k_init(const float* __restrict__ x,
                       const float* __restrict__ W1,
                       const float* __restrict__ b1,
                       const int* __restrict__ E) {
    int b = blockIdx.x;
    if (b < PROJ_BLKS) {
        __shared__ float sW[128 * 32];
        for (int i = threadIdx.x; i < 128 * 32; i += blockDim.x) sW[i] = W1[i];
        __syncthreads();
        int lane = threadIdx.x & 31;
        int warp = threadIdx.x >> 5;
        int wpb  = blockDim.x >> 5;
        float bb = b1[lane];
        for (int row = b * wpb + warp; row < N_NODES; row += PROJ_BLKS * wpb) {
            float x0 = x[row * 64 + lane];
            float x1 = x[row * 64 + 32 + lane];
            float aa = bb, ab = 0.0f;
#pragma unroll
            for (int k = 0; k < 32; k++) {
                float xv = __shfl_sync(0xffffffffu, x0, k);
                aa += xv * sW[k * 32 + lane];
                ab += xv * sW[(64 + k) * 32 + lane];
            }
#pragma unroll
            for (int k = 0; k < 32; k++) {
                float xv = __shfl_sync(0xffffffffu, x1, k);
                aa += xv * sW[(32 + k) * 32 + lane];
                ab += xv * sW[(96 + k) * 32 + lane];
            }
            g_xa[row * 32 + lane] = aa;
            g_xb[row * 32 + lane] = ab;
        }
    } else if (b < PROJ_BLKS + ZERO_BLKS) {
        int tid = (b - PROJ_BLKS) * blockDim.x + threadIdx.x;
        int nt  = ZERO_BLKS * blockDim.x;
        float4 z4 = make_float4(0.f, 0.f, 0.f, 0.f);
        float4* eb4 = reinterpret_cast<float4*>(g_eb);
        for (int i = tid; i < N_EDGES * HID / 4; i += nt) eb4[i] = z4;
    } else {
        int tid = (b - PROJ_BLKS - ZERO_BLKS) * blockDim.x + threadIdx.x;
        int nt  = CNT_BLKS * blockDim.x;
        for (int t = tid; t < NNZ / 4; t += nt) {
            int4 e4 = reinterpret_cast<const int4*>(E)[t];
            atomicAdd(&g_cnt[e4.x], 1);
            atomicAdd(&g_cnt[e4.y], 1);
            atomicAdd(&g_cnt[e4.z], 1);
            atomicAdd(&g_cnt[e4.w], 1);
        }
    }
}

// ---------------- scatter xb into per-edge sums (4 lanes / nnz) ----------------
__global__ void k_scatter(const int* __restrict__ V, const int* __restrict__ E) {
    int tid = blockIdx.x * blockDim.x + threadIdx.x;
    int g   = tid >> 2;
    int sub = tid & 3;
    if (g >= NNZ) return;
    int v = V[g], e = E[g];
    const float4* src = reinterpret_cast<const float4*>(&g_xb[v * 32]) + sub * 2;
    float4 v0 = src[0];
    float4 v1 = src[1];
    float* dst = &g_eb[e * 32 + sub * 8];
    asm volatile("red.global.add.v4.f32 [%0], {%1,%2,%3,%4};"
                 :: "l"(dst), "f"(v0.x), "f"(v0.y), "f"(v0.z), "f"(v0.w) : "memory");
    asm volatile("red.global.add.v4.f32 [%0], {%1,%2,%3,%4};"
                 :: "l"(dst + 4), "f"(v1.x), "f"(v1.y), "f"(v1.z), "f"(v1.w) : "memory");
}

// ---------------- fused MLP: probs + edge prob sums (4 lanes / nnz) ----------------
__global__ void k_logits(const int* __restrict__ V, const int* __restrict__ E,
                         const float* __restrict__ W2, const float* __restrict__ b2,
                         float* __restrict__ out_probs) {
    int tid = blockIdx.x * blockDim.x + threadIdx.x;
    int g   = tid >> 2;
    int sub = tid & 3;
    if (g >= NNZ) return;
    int v = V[g], e = E[g];
    int c = g_cnt[e];
    float ic = 1.0f / (float)(c > 1 ? c : 1);
    const float4* pa = reinterpret_cast<const float4*>(&g_xa[v * 32]) + sub * 2;
    const float4* pm = reinterpret_cast<const float4*>(&g_eb[e * 32]) + sub * 2;
    const float4* pw = reinterpret_cast<const float4*>(W2) + sub * 2;
    float4 a0 = pa[0], a1 = pa[1];
    float4 m0 = pm[0], m1 = pm[1];
    float4 w0 = pw[0], w1 = pw[1];
    float part =
        fmaxf(a0.x + m0.x * ic, 0.0f) * w0.x +
        fmaxf(a0.y + m0.y * ic, 0.0f) * w0.y +
        fmaxf(a0.z + m0.z * ic, 0.0f) * w0.z +
        fmaxf(a0.w + m0.w * ic, 0.0f) * w0.w +
        fmaxf(a1.x + m1.x * ic, 0.0f) * w1.x +
        fmaxf(a1.y + m1.y * ic, 0.0f) * w1.y +
        fmaxf(a1.z + m1.z * ic, 0.0f) * w1.z +
        fmaxf(a1.w + m1.w * ic, 0.0f) * w1.w;
    part += __shfl_xor_sync(0xffffffffu, part, 2);
    part += __shfl_xor_sync(0xffffffffu, part, 1);
    if (sub == 0) {
        float z = part + b2[0];
        float p = 1.0f / (1.0f + __expf(-z));
        out_probs[g] = p;
        asm volatile("red.global.add.f32 [%0], %1;" :: "l"(&g_sum_p[e]), "f"(p) : "memory");
    }
}

// ---------------- phase-0 histogram (full probs) ----------------
__global__ void k_hist0(const float* __restrict__ probs) {
    __shared__ unsigned sh[2048];
    for (int i = threadIdx.x; i < 2048; i += blockDim.x) sh[i] = 0u;
    __syncthreads();
    int tid = blockIdx.x * blockDim.x + threadIdx.x;
    int nt  = gridDim.x * blockDim.x;
    for (int t = tid; t < NNZ / 4; t += nt) {
        float4 p4 = reinterpret_cast<const float4*>(probs)[t];
        atomicAdd(&sh[__float_as_uint(p4.x) >> 21], 1u);
        atomicAdd(&sh[__float_as_uint(p4.y) >> 21], 1u);
        atomicAdd(&sh[__float_as_uint(p4.z) >> 21], 1u);
        atomicAdd(&sh[__float_as_uint(p4.w) >> 21], 1u);
    }
    __syncthreads();
    for (int i = threadIdx.x; i < 2048; i += blockDim.x) {
        unsigned vv = sh[i];
        if (vv) atomicAdd(&g_hist0[i], vv);
    }
}

// ---------------- compaction: local scan0 -> p1; collect candidates + hist1 ----------------
__global__ void k_compact(const float* __restrict__ probs) {
    __shared__ unsigned sA[2048], sB[2048];
    __shared__ int r_i, r_rank, r_neq;
    int nt0 = blockDim.x;
    for (int i = threadIdx.x; i < 2048; i += nt0) sA[i] = g_hist0[i];
    __syncthreads();
    pick_bucket(sA, sB, 2048, K_KEEP, true, &r_i, &r_rank, &r_neq);
    unsigned p1 = (unsigned)r_i;
    // reuse sA as phase-1 shared histogram
    for (int i = threadIdx.x; i < 2048; i += nt0) sA[i] = 0u;
    __syncthreads();

    int tid = blockIdx.x * blockDim.x + threadIdx.x;
    int nt  = gridDim.x * blockDim.x;
    int iters = (NNZ + nt - 1) / nt;
    int lane = threadIdx.x & 31;
    for (int it = 0; it < iters; it++) {
        int i = tid + it * nt;
        bool mt = false;
        unsigned bits = 0;
        if (i < NNZ) {
            bits = __float_as_uint(probs[i]);
            mt = ((bits >> 21) == p1);
        }
        unsigned ball = __ballot_sync(0xffffffffu, mt);
        if (ball) {
            int cnt = __popc(ball);
            int base = 0;
            if (lane == 0) base = atomicAdd(&g_ncand, cnt);
            base = __shfl_sync(0xffffffffu, base, 0);
            if (mt) {
                int off = __popc(ball & ((1u << lane) - 1u));
                g_cand[base + off]  = i;
                g_cbits[base + off] = bits;
                atomicAdd(&sA[(bits >> 10) & 2047u], 1u);
            }
        }
    }
    __syncthreads();
    for (int i = threadIdx.x; i < 2048; i += nt0) {
        unsigned vv = sA[i];
        if (vv) atomicAdd(&g_hist1[i], vv);
    }
}

// ---------------- single-block selection: phases 1..4 -> Tbits, cutoff ----------------
__global__ void k_sel() {
    __shared__ unsigned sA[2048], sB[2048];
    __shared__ int r_i, r_rank, r_neq;
    int tid = threadIdx.x;          // blockDim = 1024
    int nt  = blockDim.x;

    // scan0 -> p1, rank
    for (int i = tid; i < 2048; i += nt) sA[i] = g_hist0[i];
    __syncthreads();
    pick_bucket(sA, sB, 2048, K_KEEP, true, &r_i, &r_rank, &r_neq);
    unsigned p1 = (unsigned)r_i;
    int rank = r_rank;

    // scan1 -> p2, rank
    for (int i = tid; i < 2048; i += nt) sA[i] = g_hist1[i];
    __syncthreads();
    pick_bucket(sA, sB, 2048, rank, true, &r_i, &r_rank, &r_neq);
    unsigned p2 = (p1 << 11) | (unsigned)r_i;
    rank = r_rank;

    int n = g_ncand;

    // phase2: candidate pass, bins = low 10 bits
    for (int i = tid; i < 1024; i += nt) sA[i] = 0u;
    __syncthreads();
    for (int c = tid; c < n; c += nt) {
        unsigned bits = g_cbits[c];
        if ((bits >> 10) == p2) atomicAdd(&sA[bits & 1023u], 1u);
    }
    __syncthreads();
    pick_bucket(sA, sB, 1024, rank, true, &r_i, &r_rank, &r_neq);
    unsigned Tbits = (p2 << 10) | (unsigned)r_i;
    int r = r_rank, neq = r_neq;
    int cutoff;

    if (r >= neq) {
        cutoff = 0x7fffffff;    // all ties kept
    } else {
        rank = r;
        // phase3: index-high buckets among exact ties (ascending)
        for (int i = tid; i < 1024; i += nt) sA[i] = 0u;
        __syncthreads();
        for (int c = tid; c < n; c += nt) {
            if (g_cbits[c] == Tbits)
                atomicAdd(&sA[((unsigned)g_cand[c]) >> 11], 1u);
        }
        __syncthreads();
        pick_bucket(sA, sB, 1024, rank, false, &r_i, &r_rank, &r_neq);
        int ib = r_i;
        rank = r_rank;
        // phase4: index-low buckets (ascending)
        for (int i = tid; i < 2048; i += nt) sA[i] = 0u;
        __syncthreads();
        for (int c = tid; c < n; c += nt) {
            int idx = g_cand[c];
            if (g_cbits[c] == Tbits && (idx >> 11) == ib)
                atomicAdd(&sA[idx & 2047], 1u);
        }
        __syncthreads();
        pick_bucket(sA, sB, 2048, rank, false, &r_i, &r_rank, &r_neq);
        cutoff = (ib << 11) | r_i;
    }
    if (tid == 0) { g_ctrl.Tbits = Tbits; g_ctrl.cutoff = cutoff; }
}

// ---------------- hard/soft mask + edge soft sums (8 nnz / thread) ----------------
__global__ void k_mask(const int* __restrict__ E, const float* __restrict__ probs,
                       float* __restrict__ soft, float* __restrict__ hard) {
    int t = blockIdx.x * blockDim.x + threadIdx.x;
    if (t >= NNZ / 8) return;
    unsigned T = g_ctrl.Tbits;
    int cut = g_ctrl.cutoff;
#pragma unroll
    for (int half = 0; half < 2; half++) {
        int idx = t * 2 + half;
        float4 p4 = reinterpret_cast<const float4*>(probs)[idx];
        int4   e4 = reinterpret_cast<const int4*>(E)[idx];
        int base = idx * 4;
        float pv[4] = {p4.x, p4.y, p4.z, p4.w};
        int   ev[4] = {e4.x, e4.y, e4.z, e4.w};
        float sf[4], hf[4];
#pragma unroll
        for (int j = 0; j < 4; j++) {
            unsigned bits = __float_as_uint(pv[j]);
            bool h = (bits > T) || (bits == T && (base + j) <= cut);
            hf[j] = h ? 1.0f : 0.0f;
            sf[j] = h ? ((1.0f - pv[j]) + pv[j]) : 0.0f;
            if (h)
                asm volatile("red.global.add.f32 [%0], %1;"
                             :: "l"(&g_sum_s[ev[j]]), "f"(sf[j]) : "memory");
        }
        reinterpret_cast<float4*>(soft)[idx] = make_float4(sf[0], sf[1], sf[2], sf[3]);
        reinterpret_cast<float4*>(hard)[idx] = make_float4(hf[0], hf[1], hf[2], hf[3]);
    }
}

// ---------------- edge outputs (vectorized) ----------------
__global__ void k_edges(float* __restrict__ ep, float* __restrict__ es, float* __restrict__ eh) {
    int t = blockIdx.x * blockDim.x + threadIdx.x;
    if (t >= N_EDGES / 4) return;
    int4   c4 = reinterpret_cast<const int4*>(g_cnt)[t];
    float4 sp = reinterpret_cast<const float4*>(g_sum_p)[t];
    float4 ss = reinterpret_cast<const float4*>(g_sum_s)[t];
    float c0 = (float)(c4.x > 1 ? c4.x : 1);
    float c1 = (float)(c4.y > 1 ? c4.y : 1);
    float c2 = (float)(c4.z > 1 ? c4.z : 1);
    float c3 = (float)(c4.w > 1 ? c4.w : 1);
    reinterpret_cast<float4*>(ep)[t] = make_float4(sp.x / c0, sp.y / c1, sp.z / c2, sp.w / c3);
    reinterpret_cast<float4*>(es)[t] = make_float4(ss.x / c0, ss.y / c1, ss.z / c2, ss.w / c3);
    reinterpret_cast<float4*>(eh)[t] = make_float4(ss.x > 0.f ? 1.f : 0.f, ss.y > 0.f ? 1.f : 0.f,
                                                   ss.z > 0.f ? 1.f : 0.f, ss.w > 0.f ? 1.f : 0.f);
}

// ---------------- launcher ----------------
extern "C" void kernel_launch(void* const* d_in, const int* in_sizes, int n_in,
                              void* d_out, int out_size) {
    const float* x  = (const float*)d_in[0];
    const int*   V  = (const int*)d_in[1];
    const int*   E  = (const int*)d_in[2];
    const float* W1 = (const float*)d_in[3];
    const float* b1 = (const float*)d_in[4];
    const float* W2 = (const float*)d_in[5];
    const float* b2 = (const float*)d_in[6];

    float* out   = (float*)d_out;
    float* probs = out;
    float* soft  = out + NNZ;
    float* hard  = out + 2 * NNZ;
    float* ep    = out + 3 * NNZ;
    float* es    = ep + N_EDGES;
    float* eh    = es + N_EDGES;

    k_pre_a<<<256, 256>>>();                                         // 1
    k_init<<<PROJ_BLKS + ZERO_BLKS + CNT_BLKS, 256>>>(x, W1, b1, E); // 2
    k_pre_b<<<128, 256>>>();                                         // 3
    k_scatter<<<(NNZ * 4 + 255) / 256, 256>>>(V, E);                 // 4 <- profiled slot
    k_logits<<<(NNZ * 4 + 255) / 256, 256>>>(V, E, W2, b2, probs);   // 5
    k_hist0<<<512, 256>>>(probs);                                    // 6
    k_compact<<<512, 256>>>(probs);                                  // 7
    k_sel<<<1, 1024>>>();                                            // 8
    k_mask<<<(NNZ / 8 + 255) / 256, 256>>>(E, probs, soft, hard);    // 9
    k_edges<<<(N_EDGES / 4 + 255) / 256, 256>>>(ep, es, eh);         // 10
}

// round 7
// speedup vs baseline: 1.3065x; 1.3065x over previous
#include <cuda_runtime.h>
#include <cstdint>
#include <math.h>

#define N_NODES   100000
#define N_EDGES   200000
#define NNZ       2000000
#define HID       32
#define K_KEEP    1000000

#define NB     448
#define NTH    256
#define GT     (NB * NTH)
#define PROJ_B 320

// ---------------- device scratch (no allocations allowed) ----------------
__device__ __align__(16) float g_xa[N_NODES * HID];
__device__ __align__(16) float g_xb[N_NODES * HID];
__device__ __align__(16) float g_eb[N_EDGES * HID];
__device__ int      g_cnt[N_EDGES];
__device__ float    g_sum_p[N_EDGES];
__device__ float    g_sum_s[N_EDGES];
__device__ int      g_cand[NNZ];
__device__ unsigned g_cbits[NNZ];
__device__ int      g_ncand;
__device__ unsigned g_hist0[2048];
__device__ unsigned g_hist1[2048];
__device__ unsigned g_h2[1024];
__device__ unsigned g_h3[1024];
__device__ unsigned g_h4[2048];
// forwarded selection state
__device__ unsigned g_sp1;  __device__ int g_srank1;
__device__ unsigned g_sp2;  __device__ int g_srank2;
__device__ unsigned g_sT;   __device__ int g_sskip;  __device__ int g_srank3;
__device__ int      g_sib;  __device__ int g_srank4;
// grid barrier (persistent; leaves count=0, gen monotonically increasing)
__device__ unsigned g_bar_count = 0;
__device__ unsigned g_bar_gen   = 0;

__device__ __forceinline__ void grid_sync() {
    __syncthreads();
    if (threadIdx.x == 0) {
        volatile unsigned* vgen = &g_bar_gen;
        unsigned gen = *vgen;
        __threadfence();
        unsigned arrived = atomicAdd(&g_bar_count, 1u);
        if (arrived == NB - 1) {
            g_bar_count = 0;
            __threadfence();
            *vgen = gen + 1;
        } else {
            while (*vgen == gen) { }
            __threadfence();
        }
    }
    __syncthreads();
}

// scan histogram in sA (n bins), find bucket where (desc? suffix : prefix)
// cumulative first reaches `rank`. Results in shared r_i/r_rank/r_neq.
__device__ void pick_bucket(unsigned* sA, unsigned* sB, int n, int rank, bool desc,
                            int* ri, int* rr, int* rn) {
    unsigned *in = sA, *out = sB;
    for (int off = 1; off < n; off <<= 1) {
        for (int i = threadIdx.x; i < n; i += NTH) {
            unsigned add = desc ? ((i + off < n) ? in[i + off] : 0u)
                                : ((i >= off) ? in[i - off] : 0u);
            out[i] = in[i] + add;
        }
        __syncthreads();
        unsigned* t = in; in = out; out = t;
    }
    for (int i = threadIdx.x; i < n; i += NTH) {
        unsigned adj = desc ? ((i + 1 < n) ? in[i + 1] : 0u)
                            : ((i > 0) ? in[i - 1] : 0u);
        if ((int)in[i] >= rank && (int)adj < rank) {
            *ri = i; *rr = rank - (int)adj; *rn = (int)(in[i] - adj);
        }
    }
    __syncthreads();
}

__device__ __forceinline__ void load_hist(unsigned* sA, const unsigned* g, int n) {
    for (int i = threadIdx.x; i < n; i += NTH) sA[i] = g[i];
    __syncthreads();
}

__global__ void __launch_bounds__(NTH, 4)
mega(const float* __restrict__ x, const int* __restrict__ V, const int* __restrict__ E,
     const float* __restrict__ W1, const float* __restrict__ b1,
     const float* __restrict__ W2, const float* __restrict__ b2,
     float* __restrict__ probs, float* __restrict__ soft, float* __restrict__ hard,
     float* __restrict__ ep, float* __restrict__ es, float* __restrict__ eh)
{
    __shared__ unsigned shm[4096];           // 16KB: sW (proj) | sA+sB (hists)
    __shared__ int s_ri, s_rr, s_rn;
    unsigned* sA = shm;
    unsigned* sB = shm + 2048;
    int tid = threadIdx.x;
    int tg  = blockIdx.x * NTH + tid;
    int lane = tid & 31;

    // ---------- P1: zero everything ----------
    {
        float4 z4 = make_float4(0.f, 0.f, 0.f, 0.f);
        float4* eb4 = reinterpret_cast<float4*>(g_eb);
        for (int i = tg; i < N_EDGES * HID / 4; i += GT) eb4[i] = z4;
        for (int i = tg; i < N_EDGES; i += GT) { g_cnt[i] = 0; g_sum_p[i] = 0.f; g_sum_s[i] = 0.f; }
        for (int i = tg; i < 2048; i += GT) { g_hist0[i] = 0u; g_hist1[i] = 0u; g_h4[i] = 0u; }
        for (int i = tg; i < 1024; i += GT) { g_h2[i] = 0u; g_h3[i] = 0u; }
        if (tg == 0) g_ncand = 0;
    }
    grid_sync();

    // ---------- P2: proj (blocks 0..319) | count E (320..447) ----------
    if (blockIdx.x < PROJ_B) {
        float* sW = reinterpret_cast<float*>(shm);
        for (int i = tid; i < 4096; i += NTH) sW[i] = W1[i];
        __syncthreads();
        int warp = tid >> 5;
        float bb = b1[lane];
        for (int row = blockIdx.x * 8 + warp; row < N_NODES; row += PROJ_B * 8) {
            float x0 = x[row * 64 + lane];
            float x1 = x[row * 64 + 32 + lane];
            float aa = bb, ab = 0.0f;
#pragma unroll
            for (int k = 0; k < 32; k++) {
                float xv = __shfl_sync(0xffffffffu, x0, k);
                aa += xv * sW[k * 32 + lane];
                ab += xv * sW[(64 + k) * 32 + lane];
            }
#pragma unroll
            for (int k = 0; k < 32; k++) {
                float xv = __shfl_sync(0xffffffffu, x1, k);
                aa += xv * sW[(32 + k) * 32 + lane];
                ab += xv * sW[(96 + k) * 32 + lane];
            }
            g_xa[row * 32 + lane] = aa;
            g_xb[row * 32 + lane] = ab;
        }
    } else {
        int ct = (blockIdx.x - PROJ_B) * NTH + tid;
        const int CT = (NB - PROJ_B) * NTH;
        for (int t = ct; t < NNZ / 4; t += CT) {
            int4 e4 = reinterpret_cast<const int4*>(E)[t];
            atomicAdd(&g_cnt[e4.x], 1);
            atomicAdd(&g_cnt[e4.y], 1);
            atomicAdd(&g_cnt[e4.z], 1);
            atomicAdd(&g_cnt[e4.w], 1);
        }
    }
    grid_sync();

    // ---------- P3: scatter xb -> per-edge sums (4 lanes / nnz) ----------
    for (int l = tg; l < NNZ * 4; l += GT) {
        int g = l >> 2, sub = l & 3;
        int v = V[g], e = E[g];
        const float4* src = reinterpret_cast<const float4*>(&g_xb[v * 32]) + sub * 2;
        float4 v0 = src[0];
        float4 v1 = src[1];
        float* dst = &g_eb[e * 32 + sub * 8];
        asm volatile("red.global.add.v4.f32 [%0], {%1,%2,%3,%4};"
                     :: "l"(dst), "f"(v0.x), "f"(v0.y), "f"(v0.z), "f"(v0.w) : "memory");
        asm volatile("red.global.add.v4.f32 [%0], {%1,%2,%3,%4};"
                     :: "l"(dst + 4), "f"(v1.x), "f"(v1.y), "f"(v1.z), "f"(v1.w) : "memory");
    }
    grid_sync();

    // ---------- P4: logits + fused phase-0 histogram ----------
    for (int i = tid; i < 2048; i += NTH) sA[i] = 0u;
    __syncthreads();
    {
        float b2v = b2[0];
        const int iters = (NNZ * 4 + GT - 1) / GT;
        for (int it = 0; it < iters; it++) {
            int l = tg + it * GT;
            bool act = (l < NNZ * 4);
            int g = l >> 2, sub = l & 3;
            float part = 0.0f;
            int e = 0;
            if (act) {
                int v = V[g];
                e = E[g];
                int c = g_cnt[e];
                float ic = 1.0f / (float)(c > 1 ? c : 1);
                const float4* pa = reinterpret_cast<const float4*>(&g_xa[v * 32]) + sub * 2;
                const float4* pm = reinterpret_cast<const float4*>(&g_eb[e * 32]) + sub * 2;
                const float4* pw = reinterpret_cast<const float4*>(W2) + sub * 2;
                float4 a0 = pa[0], a1 = pa[1];
                float4 m0 = pm[0], m1 = pm[1];
                float4 w0 = pw[0], w1 = pw[1];
                part = fmaxf(a0.x + m0.x * ic, 0.f) * w0.x +
                       fmaxf(a0.y + m0.y * ic, 0.f) * w0.y +
                       fmaxf(a0.z + m0.z * ic, 0.f) * w0.z +
                       fmaxf(a0.w + m0.w * ic, 0.f) * w0.w +
                       fmaxf(a1.x + m1.x * ic, 0.f) * w1.x +
                       fmaxf(a1.y + m1.y * ic, 0.f) * w1.y +
                       fmaxf(a1.z + m1.z * ic, 0.f) * w1.z +
                       fmaxf(a1.w + m1.w * ic, 0.f) * w1.w;
            }
            part += __shfl_xor_sync(0xffffffffu, part, 2);
            part += __shfl_xor_sync(0xffffffffu, part, 1);
            if (act && sub == 0) {
                float z = part + b2v;
                float p = 1.0f / (1.0f + __expf(-z));
                probs[g] = p;
                atomicAdd(&sA[__float_as_uint(p) >> 21], 1u);
                asm volatile("red.global.add.f32 [%0], %1;" :: "l"(&g_sum_p[e]), "f"(p) : "memory");
            }
        }
    }
    __syncthreads();
    for (int i = tid; i < 2048; i += NTH) { unsigned v = sA[i]; if (v) atomicAdd(&g_hist0[i], v); }
    grid_sync();

    // ---------- P5: pick0 -> p1; compact candidates; build hist1 ----------
    {
        load_hist(sA, g_hist0, 2048);
        pick_bucket(sA, sB, 2048, K_KEEP, true, &s_ri, &s_rr, &s_rn);
        unsigned p1 = (unsigned)s_ri;
        int rank1 = s_rr;
        if (blockIdx.x == 0 && tid == 0) { g_sp1 = p1; g_srank1 = rank1; }
        for (int i = tid; i < 2048; i += NTH) sA[i] = 0u;
        __syncthreads();
        const int iters = (NNZ + GT - 1) / GT;
        for (int it = 0; it < iters; it++) {
            int i = tg + it * GT;
            bool mt = false;
            unsigned bits = 0;
            if (i < NNZ) {
                bits = __float_as_uint(probs[i]);
                mt = ((bits >> 21) == p1);
            }
            unsigned ball = __ballot_sync(0xffffffffu, mt);
            if (ball) {
                int cnt = __popc(ball);
                int base = 0;
                if (lane == 0) base = atomicAdd(&g_ncand, cnt);
                base = __shfl_sync(0xffffffffu, base, 0);
                if (mt) {
                    int off = __popc(ball & ((1u << lane) - 1u));
                    g_cand[base + off]  = i;
                    g_cbits[base + off] = bits;
                    atomicAdd(&sA[(bits >> 10) & 2047u], 1u);
                }
            }
        }
        __syncthreads();
        for (int i = tid; i < 2048; i += NTH) { unsigned v = sA[i]; if (v) atomicAdd(&g_hist1[i], v); }
    }
    grid_sync();

    // ---------- P6: pick1 -> p2; build h2 over candidates ----------
    {
        unsigned p1 = g_sp1;
        int rank1 = g_srank1;
        load_hist(sA, g_hist1, 2048);
        pick_bucket(sA, sB, 2048, rank1, true, &s_ri, &s_rr, &s_rn);
        unsigned p2 = (p1 << 11) | (unsigned)s_ri;
        int rank2 = s_rr;
        if (blockIdx.x == 0 && tid == 0) { g_sp2 = p2; g_srank2 = rank2; }
        for (int i = tid; i < 1024; i += NTH) sA[i] = 0u;
        __syncthreads();
        int n = g_ncand;
        for (int c = tg; c < n; c += GT) {
            unsigned bits = g_cbits[c];
            if ((bits >> 10) == p2) atomicAdd(&sA[bits & 1023u], 1u);
        }
        __syncthreads();
        for (int i = tid; i < 1024; i += NTH) { unsigned v = sA[i]; if (v) atomicAdd(&g_h2[i], v); }
    }
    grid_sync();

    // ---------- P7: pick2 -> Tbits/skip; build h3 (ties' index-high) ----------
    {
        unsigned p2 = g_sp2;
        int rank2 = g_srank2;
        load_hist(sA, g_h2, 1024);
        pick_bucket(sA, sB, 1024, rank2, true, &s_ri, &s_rr, &s_rn);
        unsigned T = (p2 << 10) | (unsigned)s_ri;
        int r = s_rr, neq = s_rn;
        int skip = (r >= neq) ? 1 : 0;
        if (blockIdx.x == 0 && tid == 0) { g_sT = T; g_sskip = skip; g_srank3 = r; }
        if (!skip) {
            for (int i = tid; i < 1024; i += NTH) sA[i] = 0u;
            __syncthreads();
            int n = g_ncand;
            for (int c = tg; c < n; c += GT) {
                if (g_cbits[c] == T) atomicAdd(&sA[((unsigned)g_cand[c]) >> 11], 1u);
            }
            __syncthreads();
            for (int i = tid; i < 1024; i += NTH) { unsigned v = sA[i]; if (v) atomicAdd(&g_h3[i], v); }
        }
    }
    grid_sync();

    // ---------- P8: pick3 -> ib; build h4 (ties' index-low) ----------
    {
        if (!g_sskip) {
            unsigned T = g_sT;
            load_hist(sA, g_h3, 1024);
            pick_bucket(sA, sB, 1024, g_srank3, false, &s_ri, &s_rr, &s_rn);
            int ib = s_ri;
            int rank4 = s_rr;
            if (blockIdx.x == 0 && tid == 0) { g_sib = ib; g_srank4 = rank4; }
            for (int i = tid; i < 2048; i += NTH) sA[i] = 0u;
            __syncthreads();
            int n = g_ncand;
            for (int c = tg; c < n; c += GT) {
                int idx = g_cand[c];
                if (g_cbits[c] == T && (idx >> 11) == ib) atomicAdd(&sA[idx & 2047], 1u);
            }
            __syncthreads();
            for (int i = tid; i < 2048; i += NTH) { unsigned v = sA[i]; if (v) atomicAdd(&g_h4[i], v); }
        }
    }
    grid_sync();

    // ---------- P9: pick4 -> cutoff; mask + edge soft sums ----------
    {
        unsigned T = g_sT;
        int cutoff;
        if (g_sskip) {
            cutoff = 0x7fffffff;
        } else {
            load_hist(sA, g_h4, 2048);
            pick_bucket(sA, sB, 2048, g_srank4, false, &s_ri, &s_rr, &s_rn);
            cutoff = (g_sib << 11) | s_ri;
        }
        for (int t = tg; t < NNZ / 4; t += GT) {
            float4 p4 = reinterpret_cast<const float4*>(probs)[t];
            int4   e4 = reinterpret_cast<const int4*>(E)[t];
            int base = t * 4;
            float pv[4] = {p4.x, p4.y, p4.z, p4.w};
            int   ev[4] = {e4.x, e4.y, e4.z, e4.w};
            float sf[4], hf[4];
#pragma unroll
            for (int j = 0; j < 4; j++) {
                unsigned bits = __float_as_uint(pv[j]);
                bool h = (bits > T) || (bits == T && (base + j) <= cutoff);
                hf[j] = h ? 1.0f : 0.0f;
                sf[j] = h ? ((1.0f - pv[j]) + pv[j]) : 0.0f;
                if (h)
                    asm volatile("red.global.add.f32 [%0], %1;"
                                 :: "l"(&g_sum_s[ev[j]]), "f"(sf[j]) : "memory");
            }
            reinterpret_cast<float4*>(soft)[t] = make_float4(sf[0], sf[1], sf[2], sf[3]);
            reinterpret_cast<float4*>(hard)[t] = make_float4(hf[0], hf[1], hf[2], hf[3]);
        }
    }
    grid_sync();

    // ---------- P10: edge outputs ----------
    for (int t = tg; t < N_EDGES / 4; t += GT) {
        int4   c4 = reinterpret_cast<const int4*>(g_cnt)[t];
        float4 sp = reinterpret_cast<const float4*>(g_sum_p)[t];
        float4 ss = reinterpret_cast<const float4*>(g_sum_s)[t];
        float c0 = (float)(c4.x > 1 ? c4.x : 1);
        float c1 = (float)(c4.y > 1 ? c4.y : 1);
        float c2 = (float)(c4.z > 1 ? c4.z : 1);
        float c3 = (float)(c4.w > 1 ? c4.w : 1);
        reinterpret_cast<float4*>(ep)[t] = make_float4(sp.x / c0, sp.y / c1, sp.z / c2, sp.w / c3);
        reinterpret_cast<float4*>(es)[t] = make_float4(ss.x / c0, ss.y / c1, ss.z / c2, ss.w / c3);
        reinterpret_cast<float4*>(eh)[t] = make_float4(ss.x > 0.f ? 1.f : 0.f, ss.y > 0.f ? 1.f : 0.f,
                                                       ss.z > 0.f ? 1.f : 0.f, ss.w > 0.f ? 1.f : 0.f);
    }
}

// ---------------- launcher ----------------
extern "C" void kernel_launch(void* const* d_in, const int* in_sizes, int n_in,
                              void* d_out, int out_size) {
    const float* x  = (const float*)d_in[0];
    const int*   V  = (const int*)d_in[1];
    const int*   E  = (const int*)d_in[2];
    const float* W1 = (const float*)d_in[3];
    const float* b1 = (const float*)d_in[4];
    const float* W2 = (const float*)d_in[5];
    const float* b2 = (const float*)d_in[6];

    float* out   = (float*)d_out;
    float* probs = out;
    float* soft  = out + NNZ;
    float* hard  = out + 2 * NNZ;
    float* ep    = out + 3 * NNZ;
    float* es    = ep + N_EDGES;
    float* eh    = es + N_EDGES;

    mega<<<NB, NTH>>>(x, V, E, W1, b1, W2, b2, probs, soft, hard, ep, es, eh);
}

// round 8
// speedup vs baseline: 1.4188x; 1.0860x over previous
#include <cuda_runtime.h>
#include <cstdint>
#include <math.h>

#define N_NODES   100000
#define N_EDGES   200000
#define NNZ       2000000
#define HID       32
#define K_KEEP    1000000

#define NB     740            // 5 blocks x 148 SMs, exact co-residency
#define NTH    256
#define GT     (NB * NTH)
#define PROJ_B 592
#define ZEND   704             // zero-eb leg: blocks [PROJ_B, ZEND)

// ---------------- device scratch (no allocations allowed) ----------------
__device__ __align__(16) float g_xa[N_NODES * HID];
__device__ __align__(16) float g_xb[N_NODES * HID];
__device__ __align__(16) float g_eb[N_EDGES * HID];
__device__ int      g_cnt[N_EDGES];
__device__ float    g_sum_p[N_EDGES];
__device__ float    g_sum_s[N_EDGES];
__device__ int      g_cand[NNZ];
__device__ unsigned g_cbits[NNZ];
__device__ int      g_ncand;
__device__ unsigned g_hist0[2048];
__device__ unsigned g_hist1[2048];
__device__ unsigned g_h2[1024];
__device__ unsigned g_h3[1024];
__device__ unsigned g_h4[2048];
// forwarded selection state
__device__ unsigned g_sp1;  __device__ int g_srank1;
__device__ unsigned g_sp2;  __device__ int g_srank2;
__device__ unsigned g_sT;   __device__ int g_sskip;  __device__ int g_srank3;
__device__ int      g_sib;  __device__ int g_srank4;
// grid barrier (persistent; leaves count=0, gen monotonically increasing)
__device__ unsigned g_bar_count = 0;
__device__ unsigned g_bar_gen   = 0;

__device__ __forceinline__ void grid_sync() {
    __syncthreads();
    if (threadIdx.x == 0) {
        volatile unsigned* vgen = &g_bar_gen;
        unsigned gen = *vgen;
        __threadfence();
        unsigned arrived = atomicAdd(&g_bar_count, 1u);
        if (arrived == NB - 1) {
            g_bar_count = 0;
            __threadfence();
            *vgen = gen + 1;
        } else {
            while (*vgen == gen) { }
            __threadfence();
        }
    }
    __syncthreads();
}

// scan histogram in sA (n bins), find bucket where (desc? suffix : prefix)
// cumulative first reaches `rank`.
__device__ void pick_bucket(unsigned* sA, unsigned* sB, int n, int rank, bool desc,
                            int* ri, int* rr, int* rn) {
    unsigned *in = sA, *out = sB;
    for (int off = 1; off < n; off <<= 1) {
        for (int i = threadIdx.x; i < n; i += NTH) {
            unsigned add = desc ? ((i + off < n) ? in[i + off] : 0u)
                                : ((i >= off) ? in[i - off] : 0u);
            out[i] = in[i] + add;
        }
        __syncthreads();
        unsigned* t = in; in = out; out = t;
    }
    for (int i = threadIdx.x; i < n; i += NTH) {
        unsigned adj = desc ? ((i + 1 < n) ? in[i + 1] : 0u)
                            : ((i > 0) ? in[i - 1] : 0u);
        if ((int)in[i] >= rank && (int)adj < rank) {
            *ri = i; *rr = rank - (int)adj; *rn = (int)(in[i] - adj);
        }
    }
    __syncthreads();
}

__device__ __forceinline__ void load_hist(unsigned* sA, const unsigned* g, int n) {
    for (int i = threadIdx.x; i < n; i += NTH) sA[i] = g[i];
    __syncthreads();
}

__global__ void __launch_bounds__(NTH, 5)
mega(const float* __restrict__ x, const int* __restrict__ V, const int* __restrict__ E,
     const float* __restrict__ W1, const float* __restrict__ b1,
     const float* __restrict__ W2, const float* __restrict__ b2,
     float* __restrict__ probs, float* __restrict__ soft, float* __restrict__ hard,
     float* __restrict__ ep, float* __restrict__ es, float* __restrict__ eh)
{
    __shared__ unsigned shm[4096];           // 16KB: sW (proj) | sA+sB (hists)
    __shared__ int s_ri, s_rr, s_rn;
    unsigned* sA = shm;
    unsigned* sB = shm + 2048;
    int tid = threadIdx.x;
    int tg  = blockIdx.x * NTH + tid;
    int lane = tid & 31;

    // ---------- P1: zero small state ----------
    {
        for (int i = tg; i < N_EDGES; i += GT) { g_cnt[i] = 0; g_sum_p[i] = 0.f; g_sum_s[i] = 0.f; }
        for (int i = tg; i < 2048; i += GT) { g_hist0[i] = 0u; g_hist1[i] = 0u; g_h4[i] = 0u; }
        for (int i = tg; i < 1024; i += GT) { g_h2[i] = 0u; g_h3[i] = 0u; }
        if (tg == 0) g_ncand = 0;
    }
    grid_sync();

    // ---------- P2: proj | zero eb | count E ----------
    if (blockIdx.x < PROJ_B) {
        float* sW = reinterpret_cast<float*>(shm);
        for (int i = tid; i < 4096; i += NTH) sW[i] = W1[i];
        __syncthreads();
        int warp = tid >> 5;
        float bb = b1[lane];
        for (int row = blockIdx.x * 8 + warp; row < N_NODES; row += PROJ_B * 8) {
            float x0 = x[row * 64 + lane];
            float x1 = x[row * 64 + 32 + lane];
            float aa = bb, ab = 0.0f;
#pragma unroll
            for (int k = 0; k < 32; k++) {
                float xv = __shfl_sync(0xffffffffu, x0, k);
                aa += xv * sW[k * 32 + lane];
                ab += xv * sW[(64 + k) * 32 + lane];
            }
#pragma unroll
            for (int k = 0; k < 32; k++) {
                float xv = __shfl_sync(0xffffffffu, x1, k);
                aa += xv * sW[(32 + k) * 32 + lane];
                ab += xv * sW[(96 + k) * 32 + lane];
            }
            g_xa[row * 32 + lane] = aa;
            g_xb[row * 32 + lane] = ab;
        }
    } else if (blockIdx.x < ZEND) {
        int zt = (blockIdx.x - PROJ_B) * NTH + tid;
        const int ZT = (ZEND - PROJ_B) * NTH;
        float4 z4 = make_float4(0.f, 0.f, 0.f, 0.f);
        float4* eb4 = reinterpret_cast<float4*>(g_eb);
        for (int i = zt; i < N_EDGES * HID / 4; i += ZT) eb4[i] = z4;
    } else {
        int ct = (blockIdx.x - ZEND) * NTH + tid;
        const int CT = (NB - ZEND) * NTH;
        for (int t = ct; t < NNZ / 4; t += CT) {
            int4 e4 = reinterpret_cast<const int4*>(E)[t];
            atomicAdd(&g_cnt[e4.x], 1);
            atomicAdd(&g_cnt[e4.y], 1);
            atomicAdd(&g_cnt[e4.z], 1);
            atomicAdd(&g_cnt[e4.w], 1);
        }
    }
    grid_sync();

    // ---------- P3: scatter xb -> per-edge sums (4 lanes / nnz) ----------
    for (int l = tg; l < NNZ * 4; l += GT) {
        int g = l >> 2, sub = l & 3;
        int v = V[g], e = E[g];
        const float4* src = reinterpret_cast<const float4*>(&g_xb[v * 32]) + sub * 2;
        float4 v0 = src[0];
        float4 v1 = src[1];
        float* dst = &g_eb[e * 32 + sub * 8];
        asm volatile("red.global.add.v4.f32 [%0], {%1,%2,%3,%4};"
                     :: "l"(dst), "f"(v0.x), "f"(v0.y), "f"(v0.z), "f"(v0.w) : "memory");
        asm volatile("red.global.add.v4.f32 [%0], {%1,%2,%3,%4};"
                     :: "l"(dst + 4), "f"(v1.x), "f"(v1.y), "f"(v1.z), "f"(v1.w) : "memory");
    }
    grid_sync();

    // ---------- P4: logits + fused phase-0 histogram ----------
    for (int i = tid; i < 2048; i += NTH) sA[i] = 0u;
    __syncthreads();
    {
        float b2v = b2[0];
        const int iters = (NNZ * 4 + GT - 1) / GT;
        for (int it = 0; it < iters; it++) {
            int l = tg + it * GT;
            bool act = (l < NNZ * 4);
            int g = l >> 2, sub = l & 3;
            float part = 0.0f;
            int e = 0;
            if (act) {
                int v = V[g];
                e = E[g];
                int c = g_cnt[e];
                float ic = 1.0f / (float)(c > 1 ? c : 1);
                const float4* pa = reinterpret_cast<const float4*>(&g_xa[v * 32]) + sub * 2;
                const float4* pm = reinterpret_cast<const float4*>(&g_eb[e * 32]) + sub * 2;
                const float4* pw = reinterpret_cast<const float4*>(W2) + sub * 2;
                float4 a0 = pa[0], a1 = pa[1];
                float4 m0 = pm[0], m1 = pm[1];
                float4 w0 = pw[0], w1 = pw[1];
                part = fmaxf(a0.x + m0.x * ic, 0.f) * w0.x +
                       fmaxf(a0.y + m0.y * ic, 0.f) * w0.y +
                       fmaxf(a0.z + m0.z * ic, 0.f) * w0.z +
                       fmaxf(a0.w + m0.w * ic, 0.f) * w0.w +
                       fmaxf(a1.x + m1.x * ic, 0.f) * w1.x +
                       fmaxf(a1.y + m1.y * ic, 0.f) * w1.y +
                       fmaxf(a1.z + m1.z * ic, 0.f) * w1.z +
                       fmaxf(a1.w + m1.w * ic, 0.f) * w1.w;
            }
            part += __shfl_xor_sync(0xffffffffu, part, 2);
            part += __shfl_xor_sync(0xffffffffu, part, 1);
            if (act && sub == 0) {
                float z = part + b2v;
                float p = 1.0f / (1.0f + __expf(-z));
                probs[g] = p;
                atomicAdd(&sA[__float_as_uint(p) >> 21], 1u);
                asm volatile("red.global.add.f32 [%0], %1;" :: "l"(&g_sum_p[e]), "f"(p) : "memory");
            }
        }
    }
    __syncthreads();
    for (int i = tid; i < 2048; i += NTH) { unsigned v = sA[i]; if (v) atomicAdd(&g_hist0[i], v); }
    grid_sync();

    // ---------- P5: pick0 -> p1; compact candidates; build hist1 ----------
    {
        load_hist(sA, g_hist0, 2048);
        pick_bucket(sA, sB, 2048, K_KEEP, true, &s_ri, &s_rr, &s_rn);
        unsigned p1 = (unsigned)s_ri;
        int rank1 = s_rr;
        if (blockIdx.x == 0 && tid == 0) { g_sp1 = p1; g_srank1 = rank1; }
        for (int i = tid; i < 2048; i += NTH) sA[i] = 0u;
        __syncthreads();
        const int iters = (NNZ + GT - 1) / GT;
        for (int it = 0; it < iters; it++) {
            int i = tg + it * GT;
            bool mt = false;
            unsigned bits = 0;
            if (i < NNZ) {
                bits = __float_as_uint(probs[i]);
                mt = ((bits >> 21) == p1);
            }
            unsigned ball = __ballot_sync(0xffffffffu, mt);
            if (ball) {
                int cnt = __popc(ball);
                int base = 0;
                if (lane == 0) base = atomicAdd(&g_ncand, cnt);
                base = __shfl_sync(0xffffffffu, base, 0);
                if (mt) {
                    int off = __popc(ball & ((1u << lane) - 1u));
                    g_cand[base + off]  = i;
                    g_cbits[base + off] = bits;
                    atomicAdd(&sA[(bits >> 10) & 2047u], 1u);
                }
            }
        }
        __syncthreads();
        for (int i = tid; i < 2048; i += NTH) { unsigned v = sA[i]; if (v) atomicAdd(&g_hist1[i], v); }
    }
    grid_sync();

    // ---------- P6: pick1 -> p2; build h2 over candidates ----------
    {
        unsigned p1 = g_sp1;
        int rank1 = g_srank1;
        load_hist(sA, g_hist1, 2048);
        pick_bucket(sA, sB, 2048, rank1, true, &s_ri, &s_rr, &s_rn);
        unsigned p2 = (p1 << 11) | (unsigned)s_ri;
        int rank2 = s_rr;
        if (blockIdx.x == 0 && tid == 0) { g_sp2 = p2; g_srank2 = rank2; }
        for (int i = tid; i < 1024; i += NTH) sA[i] = 0u;
        __syncthreads();
        int n = g_ncand;
        for (int c = tg; c < n; c += GT) {
            unsigned bits = g_cbits[c];
            if ((bits >> 10) == p2) atomicAdd(&sA[bits & 1023u], 1u);
        }
        __syncthreads();
        for (int i = tid; i < 1024; i += NTH) { unsigned v = sA[i]; if (v) atomicAdd(&g_h2[i], v); }
    }
    grid_sync();

    // ---------- P7: pick2 -> Tbits/skip; build h3 (ties' index-high) ----------
    {
        unsigned p2 = g_sp2;
        int rank2 = g_srank2;
        load_hist(sA, g_h2, 1024);
        pick_bucket(sA, sB, 1024, rank2, true, &s_ri, &s_rr, &s_rn);
        unsigned T = (p2 << 10) | (unsigned)s_ri;
        int r = s_rr, neq = s_rn;
        int skip = (r >= neq) ? 1 : 0;
        if (blockIdx.x == 0 && tid == 0) { g_sT = T; g_sskip = skip; g_srank3 = r; }
        if (!skip) {
            for (int i = tid; i < 1024; i += NTH) sA[i] = 0u;
            __syncthreads();
            int n = g_ncand;
            for (int c = tg; c < n; c += GT) {
                if (g_cbits[c] == T) atomicAdd(&sA[((unsigned)g_cand[c]) >> 11], 1u);
            }
            __syncthreads();
            for (int i = tid; i < 1024; i += NTH) { unsigned v = sA[i]; if (v) atomicAdd(&g_h3[i], v); }
        }
    }
    grid_sync();

    // ---------- P8: pick3 -> ib; build h4 (ties' index-low) ----------
    {
        if (!g_sskip) {
            unsigned T = g_sT;
            load_hist(sA, g_h3, 1024);
            pick_bucket(sA, sB, 1024, g_srank3, false, &s_ri, &s_rr, &s_rn);
            int ib = s_ri;
            int rank4 = s_rr;
            if (blockIdx.x == 0 && tid == 0) { g_sib = ib; g_srank4 = rank4; }
            for (int i = tid; i < 2048; i += NTH) sA[i] = 0u;
            __syncthreads();
            int n = g_ncand;
            for (int c = tg; c < n; c += GT) {
                int idx = g_cand[c];
                if (g_cbits[c] == T && (idx >> 11) == ib) atomicAdd(&sA[idx & 2047], 1u);
            }
            __syncthreads();
            for (int i = tid; i < 2048; i += NTH) { unsigned v = sA[i]; if (v) atomicAdd(&g_h4[i], v); }
        }
    }
    grid_sync();

    // ---------- P9: pick4 -> cutoff; mask + edge soft sums ----------
    {
        unsigned T = g_sT;
        int cutoff;
        if (g_sskip) {
            cutoff = 0x7fffffff;
        } else {
            load_hist(sA, g_h4, 2048);
            pick_bucket(sA, sB, 2048, g_srank4, false, &s_ri, &s_rr, &s_rn);
            cutoff = (g_sib << 11) | s_ri;
        }
        for (int t = tg; t < NNZ / 4; t += GT) {
            float4 p4 = reinterpret_cast<const float4*>(probs)[t];
            int4   e4 = reinterpret_cast<const int4*>(E)[t];
            int base = t * 4;
            float pv[4] = {p4.x, p4.y, p4.z, p4.w};
            int   ev[4] = {e4.x, e4.y, e4.z, e4.w};
            float sf[4], hf[4];
#pragma unroll
            for (int j = 0; j < 4; j++) {
                unsigned bits = __float_as_uint(pv[j]);
                bool h = (bits > T) || (bits == T && (base + j) <= cutoff);
                hf[j] = h ? 1.0f : 0.0f;
                sf[j] = h ? ((1.0f - pv[j]) + pv[j]) : 0.0f;
                if (h)
                    asm volatile("red.global.add.f32 [%0], %1;"
                                 :: "l"(&g_sum_s[ev[j]]), "f"(sf[j]) : "memory");
            }
            reinterpret_cast<float4*>(soft)[t] = make_float4(sf[0], sf[1], sf[2], sf[3]);
            reinterpret_cast<float4*>(hard)[t] = make_float4(hf[0], hf[1], hf[2], hf[3]);
        }
    }
    grid_sync();

    // ---------- P10: edge outputs ----------
    for (int t = tg; t < N_EDGES / 4; t += GT) {
        int4   c4 = reinterpret_cast<const int4*>(g_cnt)[t];
        float4 sp = reinterpret_cast<const float4*>(g_sum_p)[t];
        float4 ss = reinterpret_cast<const float4*>(g_sum_s)[t];
        float c0 = (float)(c4.x > 1 ? c4.x : 1);
        float c1 = (float)(c4.y > 1 ? c4.y : 1);
        float c2 = (float)(c4.z > 1 ? c4.z : 1);
        float c3 = (float)(c4.w > 1 ? c4.w : 1);
        reinterpret_cast<float4*>(ep)[t] = make_float4(sp.x / c0, sp.y / c1, sp.z / c2, sp.w / c3);
        reinterpret_cast<float4*>(es)[t] = make_float4(ss.x / c0, ss.y / c1, ss.z / c2, ss.w / c3);
        reinterpret_cast<float4*>(eh)[t] = make_float4(ss.x > 0.f ? 1.f : 0.f, ss.y > 0.f ? 1.f : 0.f,
                                                       ss.z > 0.f ? 1.f : 0.f, ss.w > 0.f ? 1.f : 0.f);
    }
}

// ---------------- launcher ----------------
extern "C" void kernel_launch(void* const* d_in, const int* in_sizes, int n_in,
                              void* d_out, int out_size) {
    const float* x  = (const float*)d_in[0];
    const int*   V  = (const int*)d_in[1];
    const int*   E  = (const int*)d_in[2];
    const float* W1 = (const float*)d_in[3];
    const float* b1 = (const float*)d_in[4];
    const float* W2 = (const float*)d_in[5];
    const float* b2 = (const float*)d_in[6];

    float* out   = (float*)d_out;
    float* probs = out;
    float* soft  = out + NNZ;
    float* hard  = out + 2 * NNZ;
    float* ep    = out + 3 * NNZ;
    float* es    = ep + N_EDGES;
    float* eh    = es + N_EDGES;

    mega<<<NB, NTH>>>(x, V, E, W1, b1, W2, b2, probs, soft, hard, ep, es, eh);
}